// round 9
// baseline (speedup 1.0000x reference)
#include <cuda_runtime.h>
#include <cuda_bf16.h>
#include <cstdint>

// ---------------- problem constants ----------------
#define C       128
#define HW      (512 * 512)
#define BATCH   4
#define TILE_PX 64
#define TILES_PER_B (HW / TILE_PX)      // 4096
#define NT      (BATCH * TILES_PER_B)   // 16384
#define THREADS 256
#define GRID    148

// ---------------- smem layout ----------------
// W planes (init only; reused as epilogue scratch afterwards)
#define W_PITCH_B  272                  // 16B-aligned (17*16), conflict-free ldsm
#define W_PLANE_B  (C * W_PITCH_B)      // 34816
#define S_W        0                    // hi plane; lo at +W_PLANE_B
#define SCRATCH_PITCH_W 76              // words (304B = 19*16): aligned + conflict-free
// X planes: [k][px] bf16, 64 px rows (128B) + 16 pad = 144B (9*16: ldsm-legal)
#define X_PITCH_B  144
#define X_PLANE_B  (C * X_PITCH_B)      // 18432
#define S_XHI      (2 * W_PLANE_B)      // 69632
#define S_XLO      (S_XHI + X_PLANE_B)  // 88064
#define SMEM_TOTAL (S_XLO + X_PLANE_B)  // 106496

typedef unsigned long long u64;

// Masked bf16 hi/lo split of W, row-major [co][k]
__device__ __nv_bfloat16 g_Whi[C * C];
__device__ __nv_bfloat16 g_Wlo[C * C];

__global__ void build_w_kernel(const float* __restrict__ w) {
    int co = blockIdx.x;
    int k  = threadIdx.x;
    float v = ((k >> 3) <= (co >> 3)) ? w[co * C + k] : 0.0f;  // HIDDEN mask
    __nv_bfloat16 h = __float2bfloat16(v);
    float r = v - __bfloat162float(h);
    g_Whi[co * C + k] = h;
    g_Wlo[co * C + k] = __float2bfloat16(r);
}

// ---------------- helpers ----------------
__device__ __forceinline__ uint32_t smem_u32(const void* p) {
    uint32_t a;
    asm("{ .reg .u64 t; cvta.to.shared.u64 t, %1; cvt.u32.u64 %0, t; }" : "=r"(a) : "l"(p));
    return a;
}
__device__ __forceinline__ uint32_t packbf2(float a, float b) {
    uint32_t r;
    asm("cvt.rn.bf16x2.f32 %0, %1, %2;" : "=r"(r) : "f"(b), "f"(a));
    return r;
}
__device__ __forceinline__ void ldsm_x4(uint32_t* r, uint32_t a) {
    asm volatile("ldmatrix.sync.aligned.m8n8.x4.shared.b16 {%0,%1,%2,%3}, [%4];"
        : "=r"(r[0]), "=r"(r[1]), "=r"(r[2]), "=r"(r[3]) : "r"(a));
}
__device__ __forceinline__ void ldsm_x4_t(uint32_t* r, uint32_t a) {
    asm volatile("ldmatrix.sync.aligned.m8n8.x4.trans.shared.b16 {%0,%1,%2,%3}, [%4];"
        : "=r"(r[0]), "=r"(r[1]), "=r"(r[2]), "=r"(r[3]) : "r"(a));
}
__device__ __forceinline__ void mma_bf16(float* d, const uint32_t* a,
                                         uint32_t b0, uint32_t b1) {
    asm volatile("mma.sync.aligned.m16n8k16.row.col.f32.bf16.bf16.f32 "
        "{%0,%1,%2,%3}, {%4,%5,%6,%7}, {%8,%9}, {%0,%1,%2,%3};"
        : "+f"(d[0]), "+f"(d[1]), "+f"(d[2]), "+f"(d[3])
        : "r"(a[0]), "r"(a[1]), "r"(a[2]), "r"(a[3]), "r"(b0), "r"(b1));
}

// 3-pass fused block: acc pair for one (A-block, B n16-tile)
__device__ __forceinline__ void mma3(float* a0, float* a1,
                                     const uint32_t* Ah, const uint32_t* Al,
                                     const uint32_t* Bh, const uint32_t* Bl) {
    mma_bf16(a0, Ah, Bh[0], Bh[1]);
    mma_bf16(a0, Ah, Bl[0], Bl[1]);
    mma_bf16(a0, Al, Bh[0], Bh[1]);
    mma_bf16(a1, Ah, Bh[2], Bh[3]);
    mma_bf16(a1, Ah, Bl[2], Bl[3]);
    mma_bf16(a1, Al, Bh[2], Bh[3]);
}

// ---------------- main persistent kernel ----------------
__global__ void __launch_bounds__(THREADS, 1)
cgconv_mma_kernel(const float* __restrict__ x,
                  const float* __restrict__ bias,
                  float* __restrict__ out)
{
    extern __shared__ char smem[];
    const uint32_t sb = smem_u32(smem);
    const int tid  = threadIdx.x;
    const int wid  = tid >> 5;      // 0..7
    const int lane = tid & 31;

    const int p  = wid & 3;         // pair id
    const int h  = wid >> 2;        // px half (32 px)
    const int m1 = p;               // small m-block
    const int m2 = 7 - p;           // large m-block

    // ---- stage W hi/lo into smem (init only) ----
    {
        const uint4* whi = reinterpret_cast<const uint4*>(g_Whi);
        const uint4* wlo = reinterpret_cast<const uint4*>(g_Wlo);
        for (int i = tid; i < C * C / 8; i += THREADS) {   // 2048 uint4
            int row = i >> 4, c = i & 15;
            *reinterpret_cast<uint4*>(smem + S_W + row * W_PITCH_B + c * 16) = whi[i];
            *reinterpret_cast<uint4*>(smem + S_W + W_PLANE_B + row * W_PITCH_B + c * 16) = wlo[i];
        }
    }
    __syncthreads();

    // ---- build register-resident A fragments (once) ----
    uint32_t A1h[4][4], A1l[4][4], A2h[8][4], A2l[8][4];
    {
        const uint32_t arow    = (uint32_t)(lane & 15) * W_PITCH_B;
        const uint32_t acolsel = (uint32_t)(lane >> 4) * 16;
        const uint32_t whi_u = sb + S_W + arow + acolsel;
        const uint32_t wlo_u = sb + S_W + W_PLANE_B + arow + acolsel;
#pragma unroll
        for (int kb = 0; kb < 4; ++kb) {
            if (kb <= m1) {
                uint32_t off = (uint32_t)m1 * 16 * W_PITCH_B + (uint32_t)kb * 32;
                ldsm_x4(A1h[kb], whi_u + off);
                ldsm_x4(A1l[kb], wlo_u + off);
            }
        }
#pragma unroll
        for (int kb = 0; kb < 8; ++kb) {
            if (kb <= m2) {
                uint32_t off = (uint32_t)m2 * 16 * W_PITCH_B + (uint32_t)kb * 32;
                ldsm_x4(A2h[kb], whi_u + off);
                ldsm_x4(A2l[kb], wlo_u + off);
            }
        }
    }
    __syncthreads();   // all A-frags built before W region becomes scratch

    // ---- bias registers ----
    const int qr = lane >> 2;
    const int qj = lane & 3;
    const float b1lo = __ldg(bias + m1 * 16 + qr);
    const float b1hi = __ldg(bias + m1 * 16 + 8 + qr);
    const float b2lo = __ldg(bias + m2 * 16 + qr);
    const float b2hi = __ldg(bias + m2 * 16 + 8 + qr);

    // ---- B ldmatrix base addresses (trans on [k][px] planes) ----
    const uint32_t brow = (uint32_t)(lane & 15) * X_PITCH_B + (uint32_t)(lane >> 4) * 16;
    const uint32_t xhi_u = sb + S_XHI + brow + (uint32_t)h * 64;   // h*32px*2B
    const uint32_t xlo_u = sb + S_XLO + brow + (uint32_t)h * 64;

    // ---- producer addressing: warp w stages k rows [16w, 16w+16) ----
    // instr i: row k = 16*wid + 2*i + (lane>>4), px = 4*(lane&15)
    const int pk_base = 16 * wid + (lane >> 4);
    const int pk_px   = (lane & 15) * 4;

    // ---- prefetch first tile ----
    uint4 pf[8];
    {
        int t0 = blockIdx.x;
        int b = t0 / TILES_PER_B;
        size_t xb = (size_t)b * C * HW + (size_t)(t0 - b * TILES_PER_B) * TILE_PX;
#pragma unroll
        for (int i = 0; i < 8; ++i)
            pf[i] = *reinterpret_cast<const uint4*>(x + xb + (size_t)(pk_base + 2 * i) * HW + pk_px);
    }

    for (int t = blockIdx.x; t < NT; t += GRID) {
        const int b   = t / TILES_PER_B;
        const int px0 = (t - b * TILES_PER_B) * TILE_PX;

        __syncthreads();   // prior tile's scratch reads + X-plane reads done

        // ---- convert prefetched regs -> bf16 hi/lo X planes ----
#pragma unroll
        for (int i = 0; i < 8; ++i) {
            const int k = pk_base + 2 * i;
            float fx = __uint_as_float(pf[i].x);
            float fy = __uint_as_float(pf[i].y);
            float fz = __uint_as_float(pf[i].z);
            float fw = __uint_as_float(pf[i].w);
            uint32_t h0 = packbf2(fx, fy);
            uint32_t h1 = packbf2(fz, fw);
            float r0 = fx - __uint_as_float(h0 << 16);
            float r1 = fy - __uint_as_float(h0 & 0xFFFF0000u);
            float r2 = fz - __uint_as_float(h1 << 16);
            float r3 = fw - __uint_as_float(h1 & 0xFFFF0000u);
            uint32_t l0 = packbf2(r0, r1);
            uint32_t l1 = packbf2(r2, r3);
            uint32_t off = (uint32_t)k * X_PITCH_B + (uint32_t)(lane & 15) * 8;
            *reinterpret_cast<uint2*>(smem + S_XHI + off) = make_uint2(h0, h1);
            *reinterpret_cast<uint2*>(smem + S_XLO + off) = make_uint2(l0, l1);
        }
        __syncthreads();

        // ---- issue next tile's prefetch ----
        {
            int tn = t + GRID;
            if (tn >= NT) tn = t;
            int bn = tn / TILES_PER_B;
            size_t xb = (size_t)bn * C * HW + (size_t)(tn - bn * TILES_PER_B) * TILE_PX;
#pragma unroll
            for (int i = 0; i < 8; ++i)
                pf[i] = *reinterpret_cast<const uint4*>(x + xb + (size_t)(pk_base + 2 * i) * HW + pk_px);
        }

        // ---- triangular GEMM: A in registers ----
        float acc[2][4][4];
#pragma unroll
        for (int mi = 0; mi < 2; ++mi)
#pragma unroll
            for (int j = 0; j < 4; ++j)
#pragma unroll
                for (int q = 0; q < 4; ++q) acc[mi][j][q] = 0.0f;

#pragma unroll
        for (int kb = 0; kb < 8; ++kb) {
            if (kb <= m2) {
#pragma unroll
                for (int nt = 0; nt < 2; ++nt) {
                    uint32_t Bh[4], Bl[4];
                    uint32_t boff = (uint32_t)kb * 16 * X_PITCH_B + (uint32_t)nt * 32;
                    ldsm_x4_t(Bh, xhi_u + boff);
                    ldsm_x4_t(Bl, xlo_u + boff);
                    mma3(acc[1][2 * nt], acc[1][2 * nt + 1], A2h[kb], A2l[kb], Bh, Bl);
                    if (kb < 4 && kb <= m1)
                        mma3(acc[0][2 * nt], acc[0][2 * nt + 1], A1h[kb], A1l[kb], Bh, Bl);
                }
            }
        }

        // ---- epilogue: bias, transpose through scratch (old W smem), STG.128 ----
#pragma unroll
        for (int j = 0; j < 4; ++j) {
            acc[0][j][0] += b1lo; acc[0][j][1] += b1lo;
            acc[0][j][2] += b1hi; acc[0][j][3] += b1hi;
            acc[1][j][0] += b2lo; acc[1][j][1] += b2lo;
            acc[1][j][2] += b2hi; acc[1][j][3] += b2hi;
        }
        float* scratch = reinterpret_cast<float*>(smem);   // pitch 76 words (304B)
#pragma unroll
        for (int mi = 0; mi < 2; ++mi) {
            const int m = mi ? m2 : m1;
            const int ch_lo = m * 16 + qr;
#pragma unroll
            for (int j = 0; j < 4; ++j) {
                const int px = h * 32 + 8 * j + 2 * qj;
                *reinterpret_cast<float2*>(scratch + ch_lo * SCRATCH_PITCH_W + px) =
                    make_float2(acc[mi][j][0], acc[mi][j][1]);
                *reinterpret_cast<float2*>(scratch + (ch_lo + 8) * SCRATCH_PITCH_W + px) =
                    make_float2(acc[mi][j][2], acc[mi][j][3]);
            }
        }
        __syncthreads();

        // coalesced read + STG.128: instr i: ch = 16*wid + 2i + (lane>>4), px = 4*(lane&15)
        const size_t obase = (size_t)b * C * HW + px0;
#pragma unroll
        for (int i = 0; i < 8; ++i) {
            const int ch = pk_base + 2 * i;
            float4 v = *reinterpret_cast<float4*>(scratch + ch * SCRATCH_PITCH_W + pk_px);
            *reinterpret_cast<float4*>(out + obase + (size_t)ch * HW + pk_px) = v;
        }
    }
}

extern "C" void kernel_launch(void* const* d_in, const int* in_sizes, int n_in,
                              void* d_out, int out_size)
{
    const float* x    = (const float*)d_in[0];
    const float* w    = (const float*)d_in[1];
    const float* bias = (const float*)d_in[2];
    float* out        = (float*)d_out;

    cudaFuncSetAttribute(cgconv_mma_kernel,
                         cudaFuncAttributeMaxDynamicSharedMemorySize, SMEM_TOTAL);

    build_w_kernel<<<C, C>>>(w);
    cgconv_mma_kernel<<<GRID, THREADS, SMEM_TOTAL>>>(x, bias, out);
}